// round 4
// baseline (speedup 1.0000x reference)
#include <cuda_runtime.h>
#include <cuda_bf16.h>
#include <stdint.h>

// ---------------------------------------------------------------------------
// Exact Chamfer via uniform-grid NN, v2.
//  - bin_kernel (1 CTA): SMEM histogram of both arrays (2x4096 cells), joint
//    exclusive scan -> flat offsets, scatter points as float4{x,y,z,orig_idx}
//    cell-contiguous into g_pts[32768]. One launch, no global zeroing.
//  - query_kernel: THREAD per query, queries taken in cell-sorted order from
//    g_pts itself -> warp-coherent shell walk, L1-hit candidates, per-candidate
//    min update for earliest pruning. Exact: box-distance pruning + shell
//    lower bound ((r-1)*cell)^2; edge cells extend to infinity (clamped
//    outliers correct). Writes g_dmin[orig_idx] -> deterministic.
//  - reduce_kernel: fixed-order double-accumulated sum.
// ---------------------------------------------------------------------------

#define NPTS   16384
#define G      16
#define NC     (G*G*G)          // 4096 cells per array
#define CELLF  0.5f
#define GMINF  (-4.0f)
#define INVC   2.0f

__device__ int2   g_meta[2 * NC];     // (flat offset, count)
__device__ float4 g_pts[2 * NPTS];    // cell-sorted, both arrays; w = orig idx
__device__ float  g_dmin[2 * NPTS];

__device__ __forceinline__ int cell_of(float v) {
    int c = (int)floorf((v - GMINF) * INVC);
    return min(G - 1, max(0, c));
}

__global__ __launch_bounds__(1024)
void bin_kernel(const float* __restrict__ pa, const float* __restrict__ pb) {
    __shared__ int h[2 * NC];     // 32 KB: counts -> then running cursors
    __shared__ int sc[1024];
    const int tid = threadIdx.x;

    for (int i = tid; i < 2 * NC; i += 1024) h[i] = 0;
    __syncthreads();

    for (int t = tid; t < 2 * NPTS; t += 1024) {
        const int arr = t >> 14, i = t & (NPTS - 1);
        const float* s = arr ? pb : pa;
        const int ci = (cell_of(s[3 * i + 2]) * G + cell_of(s[3 * i + 1])) * G
                       + cell_of(s[3 * i + 0]);
        atomicAdd(&h[arr * NC + ci], 1);
    }
    __syncthreads();

    // joint exclusive scan of 8192 counts (arr0 sums to 16384 -> arr1 offsets
    // land at 16384+, matching the flat g_pts layout)
    const int base = tid * 8;
    int c[8], tot = 0;
    #pragma unroll
    for (int k = 0; k < 8; ++k) { c[k] = h[base + k]; tot += c[k]; }
    sc[tid] = tot;
    __syncthreads();
    for (int off = 1; off < 1024; off <<= 1) {
        int v = sc[tid];
        int add = (tid >= off) ? sc[tid - off] : 0;
        __syncthreads();
        sc[tid] = v + add;
        __syncthreads();
    }
    int run = sc[tid] - tot;
    #pragma unroll
    for (int k = 0; k < 8; ++k) {
        g_meta[base + k] = make_int2(run, c[k]);
        h[base + k] = run;          // becomes scatter cursor
        run += c[k];
    }
    __syncthreads();

    for (int t = tid; t < 2 * NPTS; t += 1024) {
        const int arr = t >> 14, i = t & (NPTS - 1);
        const float* s = arr ? pb : pa;
        const float x = s[3 * i + 0], y = s[3 * i + 1], z = s[3 * i + 2];
        const int ci = (cell_of(z) * G + cell_of(y)) * G + cell_of(x);
        const int pos = atomicAdd(&h[arr * NC + ci], 1);
        g_pts[pos] = make_float4(x, y, z, __int_as_float(i));
    }
}

__global__ __launch_bounds__(128)
void query_kernel() {
    const int t = blockIdx.x * 128 + threadIdx.x;   // 0..32767, cell-sorted
    const int arr = t >> 14;
    const float4 q = g_pts[t];
    const float qx = q.x, qy = q.y, qz = q.z;
    const int2* __restrict__ meta = &g_meta[(1 - arr) * NC];
    const int cx = cell_of(qx), cy = cell_of(qy), cz = cell_of(qz);

    float cur = 3e38f;

    for (int r = 0; r < G; ++r) {
        if (r >= 1) {
            const float lb = (float)(r - 1) * CELLF;
            if (lb * lb >= cur) break;
        }
        const int x0 = max(cx - r, 0), x1 = min(cx + r, G - 1);
        const int y0 = max(cy - r, 0), y1 = min(cy + r, G - 1);
        const int z0 = max(cz - r, 0), z1 = min(cz + r, G - 1);

        for (int Z = z0; Z <= z1; ++Z) {
            const int az = (Z > cz) ? (Z - cz) : (cz - Z);
            float lo = GMINF + Z * CELLF, hi = lo + CELLF;
            float bz = 0.f;
            if (qz < lo) { if (Z > 0) bz = lo - qz; }
            else if (qz > hi) { if (Z < G - 1) bz = qz - hi; }
            const float bz2 = bz * bz;
            if (bz2 >= cur) continue;

            for (int Y = y0; Y <= y1; ++Y) {
                const int ay = (Y > cy) ? (Y - cy) : (cy - Y);
                const bool inner_yz = (az < r) && (ay < r);
                lo = GMINF + Y * CELLF; hi = lo + CELLF;
                float by = 0.f;
                if (qy < lo) { if (Y > 0) by = lo - qy; }
                else if (qy > hi) { if (Y < G - 1) by = qy - hi; }
                const float byz2 = fmaf(by, by, bz2);
                if (byz2 >= cur) continue;

                for (int X = x0; X <= x1; ++X) {
                    const int ax = (X > cx) ? (X - cx) : (cx - X);
                    if (inner_yz && ax < r) continue;   // done at smaller r
                    lo = GMINF + X * CELLF; hi = lo + CELLF;
                    float bx = 0.f;
                    if (qx < lo) { if (X > 0) bx = lo - qx; }
                    else if (qx > hi) { if (X < G - 1) bx = qx - hi; }
                    if (fmaf(bx, bx, byz2) >= cur) continue;

                    const int2 mc = __ldg(&meta[(Z * G + Y) * G + X]);
                    const int e0 = mc.x + mc.y;
                    for (int u = mc.x; u < e0; ++u) {
                        const float4 p = __ldg(&g_pts[u]);
                        const float dx = qx - p.x;
                        const float dy = qy - p.y;
                        const float dz = qz - p.z;
                        cur = fminf(cur, fmaf(dx, dx, fmaf(dy, dy, dz * dz)));
                    }
                }
            }
        }
    }
    g_dmin[arr * NPTS + __float_as_int(q.w)] = cur;
}

__global__ void reduce_kernel(float* __restrict__ out) {
    __shared__ double sm[1024];
    const int tid = threadIdx.x;
    double acc = 0.0;
    for (int i = tid; i < 2 * NPTS; i += 1024)
        acc += (double)g_dmin[i];
    sm[tid] = acc;
    __syncthreads();
    for (int o = 512; o; o >>= 1) {
        if (tid < o) sm[tid] += sm[tid + o];
        __syncthreads();
    }
    if (tid == 0) out[0] = (float)(sm[0] * (1.0 / (double)NPTS));
}

extern "C" void kernel_launch(void* const* d_in, const int* in_sizes, int n_in,
                              void* d_out, int out_size) {
    const float* p_hat = (const float*)d_in[0];  // [16384,3]
    const float* p     = (const float*)d_in[1];  // [16384,3]
    float* out = (float*)d_out;

    bin_kernel<<<1, 1024>>>(p_hat, p);
    query_kernel<<<256, 128>>>();
    reduce_kernel<<<1, 1024>>>(out);
}